// round 1
// baseline (speedup 1.0000x reference)
#include <cuda_runtime.h>

#define BB 16
#define CC 512
#define TT 1024
#define NH 8
#define DH 64
#define NG 32
#define CPG 16  // channels per group

// Scratch (statics are the sanctioned alloc-free workaround)
__device__ float g_xn[BB * CC * TT];        // 32 MB
__device__ float g_qkv[BB * 3 * CC * TT];   // 96 MB
__device__ float g_attn[BB * CC * TT];      // 32 MB

// ---------------------------------------------------------------------------
// GroupNorm: one block per (batch, group). 16 ch x 1024 t = 16384 elems.
// ---------------------------------------------------------------------------
__global__ __launch_bounds__(256) void gn_kernel(
    const float* __restrict__ x, const float* __restrict__ scale,
    const float* __restrict__ bias, float* __restrict__ xn) {
    int blk = blockIdx.x;
    int b = blk >> 5, g = blk & 31;
    const float* xp = x + ((size_t)b * CC + (size_t)g * CPG) * TT;
    float* xnp = xn + ((size_t)b * CC + (size_t)g * CPG) * TT;

    float s = 0.f, ss = 0.f;
    for (int i = threadIdx.x; i < CPG * TT; i += 256) {
        float v = xp[i];
        s += v;
        ss += v * v;
    }
    // warp + block reduce
    for (int o = 16; o; o >>= 1) {
        s += __shfl_down_sync(0xffffffffu, s, o);
        ss += __shfl_down_sync(0xffffffffu, ss, o);
    }
    __shared__ float red0[8], red1[8];
    __shared__ float mean_s, inv_s;
    int warp = threadIdx.x >> 5, lane = threadIdx.x & 31;
    if (lane == 0) { red0[warp] = s; red1[warp] = ss; }
    __syncthreads();
    if (threadIdx.x == 0) {
        float S = 0.f, SS = 0.f;
        #pragma unroll
        for (int w = 0; w < 8; w++) { S += red0[w]; SS += red1[w]; }
        const float invn = 1.f / (float)(CPG * TT);
        float mean = S * invn;
        float var = SS * invn - mean * mean;
        mean_s = mean;
        inv_s = rsqrtf(var + 1e-5f);
    }
    __syncthreads();
    float mean = mean_s, inv = inv_s;
    for (int i = threadIdx.x; i < CPG * TT; i += 256) {
        int ch = g * CPG + (i >> 10);
        xnp[i] = (xp[i] - mean) * inv * scale[ch] + bias[ch];
    }
}

// ---------------------------------------------------------------------------
// Batched GEMM: out[b] (MxN) = W (MxK) @ X[b] (KxN) + bias[m] (+ residual)
// N = TT = 1024. Tile 64x64x16, 256 threads, 4x4 microtile.
// ---------------------------------------------------------------------------
__global__ __launch_bounds__(256) void gemm_kernel(
    const float* __restrict__ W, const float* __restrict__ X,
    const float* __restrict__ bias, const float* __restrict__ res,
    float* __restrict__ out, int M, int K) {
    const int N = TT;
    int bb = blockIdx.z;
    const float* Xb = X + (size_t)bb * K * N;
    float* Ob = out + (size_t)bb * M * N;
    const float* Rb = res ? res + (size_t)bb * M * N : nullptr;

    __shared__ float As[16][68];  // [k][m], pad keeps float4 alignment + no conflicts
    __shared__ float Bs[16][64];  // [k][n]

    int tid = threadIdx.x;
    int tx = tid & 15, ty = tid >> 4;
    int m0 = blockIdx.y * 64, n0 = blockIdx.x * 64;

    float acc[4][4] = {};

    for (int k0 = 0; k0 < K; k0 += 16) {
        #pragma unroll
        for (int it = 0; it < 4; it++) {
            int e = tid + it * 256;
            int m = e >> 4, k = e & 15;
            As[k][m] = W[(size_t)(m0 + m) * K + k0 + k];
        }
        #pragma unroll
        for (int it = 0; it < 4; it++) {
            int e = tid + it * 256;
            int k = e >> 6, n = e & 63;
            Bs[k][n] = Xb[(size_t)(k0 + k) * N + n0 + n];
        }
        __syncthreads();
        #pragma unroll
        for (int k = 0; k < 16; k++) {
            float a[4], bv[4];
            #pragma unroll
            for (int i = 0; i < 4; i++) a[i] = As[k][ty * 4 + i];
            #pragma unroll
            for (int j = 0; j < 4; j++) bv[j] = Bs[k][tx * 4 + j];
            #pragma unroll
            for (int i = 0; i < 4; i++)
                #pragma unroll
                for (int j = 0; j < 4; j++) acc[i][j] += a[i] * bv[j];
        }
        __syncthreads();
    }

    #pragma unroll
    for (int i = 0; i < 4; i++) {
        int m = m0 + ty * 4 + i;
        float bi = bias[m];
        #pragma unroll
        for (int j = 0; j < 4; j++) {
            int n = n0 + tx * 4 + j;
            float v = acc[i][j] + bi;
            if (Rb) v += Rb[(size_t)m * N + n];
            Ob[(size_t)m * N + n] = v;
        }
    }
}

// ---------------------------------------------------------------------------
// Attention: one block per (head, 64-query tile). Online softmax over 16
// key tiles of 64. qkv layout: [b, 3*CC, TT]; head hd rows at hd*192.
// ---------------------------------------------------------------------------
#define QS_STRIDE 68
#define VS_STRIDE 65
// smem floats: Qs 64*68 + Ks 64*68 + Vs 64*65 + Ss 64*68 + 3*64
#define ATTN_SMEM_FLOATS (64 * 68 * 3 + 64 * 65 + 192)

__global__ __launch_bounds__(256) void attn_kernel(
    const float* __restrict__ qkv, float* __restrict__ attn) {
    extern __shared__ float sm[];
    float* Qs = sm;                      // [c][q] stride 68
    float* Ks = Qs + 64 * QS_STRIDE;     // [c][s] stride 68
    float* Vs = Ks + 64 * QS_STRIDE;     // [s][c] stride 65
    float* Ss = Vs + 64 * VS_STRIDE;     // [q][s] stride 68 (reused as [c][q] s65 at end)
    float* m_s = Ss + 64 * QS_STRIDE;
    float* l_s = m_s + 64;
    float* al_s = l_s + 64;

    int tid = threadIdx.x;
    int tx = tid & 15, ty = tid >> 4;
    int head = blockIdx.y;
    int b = head >> 3, hd = head & 7;
    int q0g = blockIdx.x * 64;

    const float* qp = qkv + ((size_t)b * 3 * CC + (size_t)hd * 192) * TT;
    const float* kp = qp + (size_t)64 * TT;
    const float* vp = kp + (size_t)64 * TT;

    #pragma unroll
    for (int it = 0; it < 16; it++) {
        int e = tid + it * 256;
        int c = e >> 6, q = e & 63;
        Qs[c * QS_STRIDE + q] = qp[(size_t)c * TT + q0g + q];
    }
    if (tid < 64) { m_s[tid] = -1e30f; l_s[tid] = 0.f; }
    float o[4][4] = {};
    __syncthreads();

    for (int kt = 0; kt < TT / 64; kt++) {
        int s0g = kt * 64;
        #pragma unroll
        for (int it = 0; it < 16; it++) {
            int e = tid + it * 256;
            int c = e >> 6, s = e & 63;
            float kv = kp[(size_t)c * TT + s0g + s];
            float vv = vp[(size_t)c * TT + s0g + s];
            Ks[c * QS_STRIDE + s] = kv;
            Vs[s * VS_STRIDE + c] = vv;
        }
        __syncthreads();

        // S = (Q^T K) * dh^-0.5
        {
            float acc[4][4] = {};
            #pragma unroll 8
            for (int c = 0; c < 64; c++) {
                float a[4], bv[4];
                #pragma unroll
                for (int i = 0; i < 4; i++) a[i] = Qs[c * QS_STRIDE + ty * 4 + i];
                #pragma unroll
                for (int j = 0; j < 4; j++) bv[j] = Ks[c * QS_STRIDE + tx * 4 + j];
                #pragma unroll
                for (int i = 0; i < 4; i++)
                    #pragma unroll
                    for (int j = 0; j < 4; j++) acc[i][j] += a[i] * bv[j];
            }
            #pragma unroll
            for (int i = 0; i < 4; i++)
                #pragma unroll
                for (int j = 0; j < 4; j++)
                    Ss[(ty * 4 + i) * QS_STRIDE + tx * 4 + j] = acc[i][j] * 0.125f;
        }
        __syncthreads();

        // online softmax per query row
        if (tid < 64) {
            int q = tid;
            float* row = Ss + q * QS_STRIDE;
            float mprev = m_s[q];
            float mx = mprev;
            #pragma unroll 8
            for (int s = 0; s < 64; s++) mx = fmaxf(mx, row[s]);
            float alpha = __expf(mprev - mx);
            float sum = 0.f;
            #pragma unroll 8
            for (int s = 0; s < 64; s++) {
                float p = __expf(row[s] - mx);
                row[s] = p;
                sum += p;
            }
            m_s[q] = mx;
            l_s[q] = l_s[q] * alpha + sum;
            al_s[q] = alpha;
        }
        __syncthreads();

        // O = O*alpha + P @ V
        {
            float al[4];
            #pragma unroll
            for (int i = 0; i < 4; i++) al[i] = al_s[ty * 4 + i];
            #pragma unroll
            for (int i = 0; i < 4; i++)
                #pragma unroll
                for (int j = 0; j < 4; j++) o[i][j] *= al[i];
            #pragma unroll 8
            for (int s = 0; s < 64; s++) {
                float p[4], v[4];
                #pragma unroll
                for (int i = 0; i < 4; i++) p[i] = Ss[(ty * 4 + i) * QS_STRIDE + s];
                #pragma unroll
                for (int j = 0; j < 4; j++) v[j] = Vs[s * VS_STRIDE + tx * 4 + j];
                #pragma unroll
                for (int i = 0; i < 4; i++)
                    #pragma unroll
                    for (int j = 0; j < 4; j++) o[i][j] += p[i] * v[j];
            }
        }
        __syncthreads();
    }

    // normalize, stage transposed into smem ([c][q], stride 65), coalesced store
    {
        float linv[4];
        #pragma unroll
        for (int i = 0; i < 4; i++) linv[i] = 1.f / l_s[ty * 4 + i];
        #pragma unroll
        for (int i = 0; i < 4; i++)
            #pragma unroll
            for (int j = 0; j < 4; j++)
                Ss[(tx * 4 + j) * VS_STRIDE + ty * 4 + i] = o[i][j] * linv[i];
    }
    __syncthreads();
    float* op = attn + ((size_t)b * CC + (size_t)hd * 64) * TT + q0g;
    #pragma unroll
    for (int it = 0; it < 16; it++) {
        int e = tid + it * 256;
        int c = e >> 6, q = e & 63;
        op[(size_t)c * TT + q] = Ss[c * VS_STRIDE + q];
    }
}

// ---------------------------------------------------------------------------
extern "C" void kernel_launch(void* const* d_in, const int* in_sizes, int n_in,
                              void* d_out, int out_size) {
    const float* x = (const float*)d_in[0];
    const float* gn_scale = (const float*)d_in[1];
    const float* gn_bias = (const float*)d_in[2];
    const float* w_qkv = (const float*)d_in[3];
    const float* b_qkv = (const float*)d_in[4];
    const float* w_proj = (const float*)d_in[5];
    const float* b_proj = (const float*)d_in[6];
    float* out = (float*)d_out;

    float *xn, *qkv, *attn;
    cudaGetSymbolAddress((void**)&xn, g_xn);
    cudaGetSymbolAddress((void**)&qkv, g_qkv);
    cudaGetSymbolAddress((void**)&attn, g_attn);

    const int attn_smem = ATTN_SMEM_FLOATS * sizeof(float);
    cudaFuncSetAttribute(attn_kernel, cudaFuncAttributeMaxDynamicSharedMemorySize,
                         attn_smem);

    // 1) GroupNorm
    gn_kernel<<<BB * NG, 256>>>(x, gn_scale, gn_bias, xn);
    // 2) QKV: (1536x512)@(512x1024) per batch
    gemm_kernel<<<dim3(TT / 64, (3 * CC) / 64, BB), 256>>>(
        w_qkv, xn, b_qkv, nullptr, qkv, 3 * CC, CC);
    // 3) Attention: 128 heads x 16 query tiles
    attn_kernel<<<dim3(TT / 64, BB * NH), 256, attn_smem>>>(qkv, attn);
    // 4) Proj + bias + residual -> out
    gemm_kernel<<<dim3(TT / 64, CC / 64, BB), 256>>>(
        w_proj, attn, b_proj, x, out, CC, CC);
}

// round 2
// speedup vs baseline: 1.1678x; 1.1678x over previous
#include <cuda_runtime.h>

#define BB 16
#define CC 512
#define TT 1024
#define NH 8
#define DH 64
#define NG 32
#define CPG 16

typedef unsigned long long u64;

__device__ __forceinline__ u64 dup2(float v) {
    u64 r; asm("mov.b64 %0,{%1,%1};" : "=l"(r) : "f"(v)); return r;
}
__device__ __forceinline__ void fma2(u64& d, u64 a, u64 b) {
    asm("fma.rn.f32x2 %0,%1,%2,%3;" : "=l"(d) : "l"(a), "l"(b), "l"(d));
}
__device__ __forceinline__ u64 mul2(u64 a, u64 b) {
    u64 r; asm("mul.rn.f32x2 %0,%1,%2;" : "=l"(r) : "l"(a), "l"(b)); return r;
}
__device__ __forceinline__ float2 unpk(u64 v) {
    float2 f; asm("mov.b64 {%0,%1},%2;" : "=f"(f.x), "=f"(f.y) : "l"(v)); return f;
}

// Scratch
__device__ float g_xn[BB * CC * TT];
__device__ float g_qkv[BB * 3 * CC * TT];
__device__ float g_attn[BB * CC * TT];

// ---------------------------------------------------------------------------
// GroupNorm
// ---------------------------------------------------------------------------
__global__ __launch_bounds__(256) void gn_kernel(
    const float* __restrict__ x, const float* __restrict__ scale,
    const float* __restrict__ bias, float* __restrict__ xn) {
    int blk = blockIdx.x;
    int b = blk >> 5, g = blk & 31;
    const float4* xp4 = (const float4*)(x + ((size_t)b * CC + (size_t)g * CPG) * TT);
    float4* xnp4 = (float4*)(xn + ((size_t)b * CC + (size_t)g * CPG) * TT);
    const int N4 = CPG * TT / 4;

    float s = 0.f, ss = 0.f;
    for (int i = threadIdx.x; i < N4; i += 256) {
        float4 v = xp4[i];
        s += v.x + v.y + v.z + v.w;
        ss += v.x * v.x + v.y * v.y + v.z * v.z + v.w * v.w;
    }
    for (int o = 16; o; o >>= 1) {
        s += __shfl_down_sync(0xffffffffu, s, o);
        ss += __shfl_down_sync(0xffffffffu, ss, o);
    }
    __shared__ float red0[8], red1[8];
    __shared__ float mean_s, inv_s;
    int warp = threadIdx.x >> 5, lane = threadIdx.x & 31;
    if (lane == 0) { red0[warp] = s; red1[warp] = ss; }
    __syncthreads();
    if (threadIdx.x == 0) {
        float S = 0.f, SS = 0.f;
        #pragma unroll
        for (int w = 0; w < 8; w++) { S += red0[w]; SS += red1[w]; }
        const float invn = 1.f / (float)(CPG * TT);
        float mean = S * invn;
        float var = SS * invn - mean * mean;
        mean_s = mean;
        inv_s = rsqrtf(var + 1e-5f);
    }
    __syncthreads();
    float mean = mean_s, inv = inv_s;
    for (int i = threadIdx.x; i < N4; i += 256) {
        int ch = g * CPG + (i >> 8);  // 256 float4 per channel row
        float sc = scale[ch] * inv, bi = bias[ch] - mean * sc;
        float4 v = xp4[i];
        v.x = v.x * sc + bi; v.y = v.y * sc + bi;
        v.z = v.z * sc + bi; v.w = v.w * sc + bi;
        xnp4[i] = v;
    }
}

// ---------------------------------------------------------------------------
// GEMM: out[b](MxN) = W(MxK) @ X[b](KxN) + bias (+res). N=1024.
// 128x128x16 tiles, 256 threads, 8x8 microtile, f32x2 packed FMA,
// double-buffered smem with register prefetch.
// ---------------------------------------------------------------------------
__global__ __launch_bounds__(256, 2) void gemm_kernel(
    const float* __restrict__ W, const float* __restrict__ X,
    const float* __restrict__ bias, const float* __restrict__ res,
    float* __restrict__ out, int M, int K) {
    const int N = TT;
    int bb = blockIdx.z;
    const float* Xb = X + (size_t)bb * K * N;
    float* Ob = out + (size_t)bb * M * N;
    const float* Rb = res ? res + (size_t)bb * M * N : nullptr;

    __shared__ float As[2][16][132];  // [k][m]
    __shared__ float Bs[2][16][128];  // [k][n]

    int tid = threadIdx.x;
    int tx = tid & 15, ty = tid >> 4;
    int m0 = blockIdx.y * 128, n0 = blockIdx.x * 128;

    // load indices
    int kw = tid & 15, mw = tid >> 4;          // W: 8 loads, m = mw + it*16
    int e0 = tid, e1 = tid + 256;              // X: 2 float4 loads
    int kx0 = e0 >> 5, c40 = e0 & 31;
    int kx1 = e1 >> 5, c41 = e1 & 31;

    float ra[8];
    float4 rb0, rb1;
    const int NT = K / 16;

    auto gload = [&](int kt) {
        const float* wp = W + (size_t)(m0 + mw) * K + kt * 16 + kw;
        #pragma unroll
        for (int it = 0; it < 8; it++) ra[it] = wp[(size_t)it * 16 * K];
        rb0 = *(const float4*)&Xb[(size_t)(kt * 16 + kx0) * N + n0 + c40 * 4];
        rb1 = *(const float4*)&Xb[(size_t)(kt * 16 + kx1) * N + n0 + c41 * 4];
    };
    auto sstore = [&](int buf) {
        #pragma unroll
        for (int it = 0; it < 8; it++) As[buf][kw][mw + it * 16] = ra[it];
        *(float4*)&Bs[buf][kx0][c40 * 4] = rb0;
        *(float4*)&Bs[buf][kx1][c41 * 4] = rb1;
    };

    u64 acc[8][4];
    #pragma unroll
    for (int i = 0; i < 8; i++)
        #pragma unroll
        for (int j = 0; j < 4; j++) acc[i][j] = 0ull;

    gload(0);
    sstore(0);
    __syncthreads();

    for (int kt = 0; kt < NT; kt++) {
        int cur = kt & 1;
        if (kt + 1 < NT) gload(kt + 1);
        #pragma unroll
        for (int k = 0; k < 16; k++) {
            float4 a0 = *(const float4*)&As[cur][k][ty * 8];
            float4 a1 = *(const float4*)&As[cur][k][ty * 8 + 4];
            ulonglong2 bb0 = *(const ulonglong2*)&Bs[cur][k][tx * 8];
            ulonglong2 bb1 = *(const ulonglong2*)&Bs[cur][k][tx * 8 + 4];
            u64 b2[4] = {bb0.x, bb0.y, bb1.x, bb1.y};
            float av[8] = {a0.x, a0.y, a0.z, a0.w, a1.x, a1.y, a1.z, a1.w};
            #pragma unroll
            for (int i = 0; i < 8; i++) {
                u64 ai = dup2(av[i]);
                #pragma unroll
                for (int j = 0; j < 4; j++) fma2(acc[i][j], ai, b2[j]);
            }
        }
        if (kt + 1 < NT) {
            sstore(cur ^ 1);
            __syncthreads();
        }
    }

    #pragma unroll
    for (int i = 0; i < 8; i++) {
        int m = m0 + ty * 8 + i;
        float bi = bias[m];
        float2 p0 = unpk(acc[i][0]), p1 = unpk(acc[i][1]);
        float2 p2 = unpk(acc[i][2]), p3 = unpk(acc[i][3]);
        float4 v0 = {p0.x + bi, p0.y + bi, p1.x + bi, p1.y + bi};
        float4 v1 = {p2.x + bi, p2.y + bi, p3.x + bi, p3.y + bi};
        size_t base = (size_t)m * N + n0 + tx * 8;
        if (Rb) {
            float4 r0 = *(const float4*)&Rb[base];
            float4 r1 = *(const float4*)&Rb[base + 4];
            v0.x += r0.x; v0.y += r0.y; v0.z += r0.z; v0.w += r0.w;
            v1.x += r1.x; v1.y += r1.y; v1.z += r1.z; v1.w += r1.w;
        }
        *(float4*)&Ob[base] = v0;
        *(float4*)&Ob[base + 4] = v1;
    }
}

// ---------------------------------------------------------------------------
// Attention: block per (head, 64-query tile). K/V tiles of 64, online softmax.
// QK and PV with f32x2. V kept [c][s] (dot-product PV, no transpose).
// ---------------------------------------------------------------------------
#define AST 68  // smem row stride (floats); 68*4=272 bytes, 16B-aligned
#define ATTN_SMEM_FLOATS (4 * 64 * AST + 192)

__global__ __launch_bounds__(256) void attn_kernel(
    const float* __restrict__ qkv, float* __restrict__ attn) {
    extern __shared__ float sm[];
    float* Qs = sm;                 // [c][q]
    float* Ks = Qs + 64 * AST;      // [c][s]
    float* Vs = Ks + 64 * AST;      // [c][s]
    float* Ss = Vs + 64 * AST;      // [q][s], reused as [c][q] at end
    float* m_s = Ss + 64 * AST;
    float* l_s = m_s + 64;
    float* al_s = l_s + 64;

    int tid = threadIdx.x;
    int tx = tid & 15, ty = tid >> 4;
    int head = blockIdx.y;
    int b = head >> 3, hd = head & 7;
    int q0g = blockIdx.x * 64;

    const float* qp = qkv + ((size_t)b * 3 * CC + (size_t)hd * 192) * TT;
    const float* kp = qp + (size_t)64 * TT;
    const float* vp = kp + (size_t)64 * TT;

    // load Q tile: [c][q]
    #pragma unroll
    for (int it = 0; it < 4; it++) {
        int e = tid + it * 256;
        int c = e >> 4, s4 = e & 15;
        *(float4*)&Qs[c * AST + s4 * 4] =
            *(const float4*)&qp[(size_t)c * TT + q0g + s4 * 4];
    }
    if (tid < 64) { m_s[tid] = -1e30f; l_s[tid] = 0.f; }

    u64 o2[4][4];  // [q_i][c_j] pairwise partial sums over s
    #pragma unroll
    for (int i = 0; i < 4; i++)
        #pragma unroll
        for (int j = 0; j < 4; j++) o2[i][j] = 0ull;
    __syncthreads();

    for (int kt = 0; kt < TT / 64; kt++) {
        int s0g = kt * 64;
        #pragma unroll
        for (int it = 0; it < 4; it++) {
            int e = tid + it * 256;
            int c = e >> 4, s4 = e & 15;
            *(float4*)&Ks[c * AST + s4 * 4] =
                *(const float4*)&kp[(size_t)c * TT + s0g + s4 * 4];
            *(float4*)&Vs[c * AST + s4 * 4] =
                *(const float4*)&vp[(size_t)c * TT + s0g + s4 * 4];
        }
        __syncthreads();

        // S[q][s] = (Q^T K) * 0.125 ; q = ty*4+i, s = tx*4 + pairs
        {
            u64 acc[4][2];
            #pragma unroll
            for (int i = 0; i < 4; i++) { acc[i][0] = 0ull; acc[i][1] = 0ull; }
            #pragma unroll 8
            for (int c = 0; c < 64; c++) {
                float4 a = *(const float4*)&Qs[c * AST + ty * 4];
                ulonglong2 kk = *(const ulonglong2*)&Ks[c * AST + tx * 4];
                float av[4] = {a.x, a.y, a.z, a.w};
                #pragma unroll
                for (int i = 0; i < 4; i++) {
                    u64 ai = dup2(av[i]);
                    fma2(acc[i][0], ai, kk.x);
                    fma2(acc[i][1], ai, kk.y);
                }
            }
            #pragma unroll
            for (int i = 0; i < 4; i++) {
                float2 p0 = unpk(acc[i][0]), p1 = unpk(acc[i][1]);
                float4 v = {p0.x * 0.125f, p0.y * 0.125f, p1.x * 0.125f, p1.y * 0.125f};
                *(float4*)&Ss[(ty * 4 + i) * AST + tx * 4] = v;
            }
        }
        __syncthreads();

        // online softmax: 4 threads per row
        {
            int q = tid >> 2, part = tid & 3;
            float* row = Ss + q * AST + part * 16;
            float mprev = m_s[q];
            float mx = -1e30f;
            #pragma unroll
            for (int s = 0; s < 16; s++) mx = fmaxf(mx, row[s]);
            mx = fmaxf(mx, __shfl_xor_sync(0xffffffffu, mx, 1));
            mx = fmaxf(mx, __shfl_xor_sync(0xffffffffu, mx, 2));
            mx = fmaxf(mx, mprev);
            float sum = 0.f;
            #pragma unroll
            for (int s = 0; s < 16; s++) {
                float p = __expf(row[s] - mx);
                row[s] = p;
                sum += p;
            }
            sum += __shfl_xor_sync(0xffffffffu, sum, 1);
            sum += __shfl_xor_sync(0xffffffffu, sum, 2);
            if (part == 0) {
                float al = __expf(mprev - mx);
                m_s[q] = mx;
                al_s[q] = al;
                l_s[q] = l_s[q] * al + sum;
            }
        }
        __syncthreads();

        // O2 = O2*alpha + P @ V^T (dot over s). q = ty*4+i, c = j*16+tx.
        {
            #pragma unroll
            for (int i = 0; i < 4; i++) {
                u64 ai = dup2(al_s[ty * 4 + i]);
                #pragma unroll
                for (int j = 0; j < 4; j++) o2[i][j] = mul2(o2[i][j], ai);
            }
            #pragma unroll 4
            for (int s4 = 0; s4 < 16; s4++) {
                ulonglong2 p[4];
                #pragma unroll
                for (int i = 0; i < 4; i++)
                    p[i] = *(const ulonglong2*)&Ss[(ty * 4 + i) * AST + s4 * 4];
                #pragma unroll
                for (int j = 0; j < 4; j++) {
                    ulonglong2 v = *(const ulonglong2*)&Vs[(j * 16 + tx) * AST + s4 * 4];
                    #pragma unroll
                    for (int i = 0; i < 4; i++) {
                        fma2(o2[i][j], p[i].x, v.x);
                        fma2(o2[i][j], p[i].y, v.y);
                    }
                }
            }
        }
        __syncthreads();
    }

    // normalize + stage transposed [c][q] into Ss, then coalesced store
    {
        float linv[4];
        #pragma unroll
        for (int i = 0; i < 4; i++) linv[i] = 1.f / l_s[ty * 4 + i];
        #pragma unroll
        for (int j = 0; j < 4; j++) {
            float vq[4];
            #pragma unroll
            for (int i = 0; i < 4; i++) {
                float2 pp = unpk(o2[i][j]);
                vq[i] = (pp.x + pp.y) * linv[i];
            }
            float4 v = {vq[0], vq[1], vq[2], vq[3]};
            *(float4*)&Ss[(j * 16 + tx) * AST + ty * 4] = v;
        }
    }
    __syncthreads();
    float* op = attn + ((size_t)b * CC + (size_t)hd * 64) * TT + q0g;
    #pragma unroll
    for (int it = 0; it < 4; it++) {
        int e = tid + it * 256;
        int c = e >> 4, q4 = e & 15;
        *(float4*)&op[(size_t)c * TT + q4 * 4] =
            *(const float4*)&Ss[c * AST + q4 * 4];
    }
}

// ---------------------------------------------------------------------------
extern "C" void kernel_launch(void* const* d_in, const int* in_sizes, int n_in,
                              void* d_out, int out_size) {
    const float* x = (const float*)d_in[0];
    const float* gn_scale = (const float*)d_in[1];
    const float* gn_bias = (const float*)d_in[2];
    const float* w_qkv = (const float*)d_in[3];
    const float* b_qkv = (const float*)d_in[4];
    const float* w_proj = (const float*)d_in[5];
    const float* b_proj = (const float*)d_in[6];
    float* out = (float*)d_out;

    float *xn, *qkv, *attn;
    cudaGetSymbolAddress((void**)&xn, g_xn);
    cudaGetSymbolAddress((void**)&qkv, g_qkv);
    cudaGetSymbolAddress((void**)&attn, g_attn);

    const int attn_smem = ATTN_SMEM_FLOATS * sizeof(float);
    cudaFuncSetAttribute(attn_kernel, cudaFuncAttributeMaxDynamicSharedMemorySize,
                         attn_smem);

    gn_kernel<<<BB * NG, 256>>>(x, gn_scale, gn_bias, xn);
    gemm_kernel<<<dim3(TT / 128, (3 * CC) / 128, BB), 256>>>(
        w_qkv, xn, b_qkv, nullptr, qkv, 3 * CC, CC);
    attn_kernel<<<dim3(TT / 64, BB * NH), 256, attn_smem>>>(qkv, attn);
    gemm_kernel<<<dim3(TT / 128, CC / 128, BB), 256>>>(
        w_proj, attn, b_proj, x, out, CC, CC);
}

// round 6
// speedup vs baseline: 2.5102x; 2.1495x over previous
#include <cuda_runtime.h>
#include <cuda_bf16.h>
#include <cstdint>

#define BB 16
#define CC 512
#define TT 1024
#define NH 8
#define DH 64
#define NG 32
#define CPG 16

// ---------------- scratch ----------------
__device__ float g_xn[BB * CC * TT];
__device__ float g_qkv[BB * 3 * CC * TT];
__device__ float g_attn[BB * CC * TT];

// ---------------- helpers ----------------
__device__ __forceinline__ uint32_t cvta_smem(const void* p) {
    uint32_t a;
    asm("{.reg .u64 t; cvta.to.shared.u64 t, %1; cvt.u32.u64 %0, t;}"
        : "=r"(a) : "l"(p));
    return a;
}
__device__ __forceinline__ void ldsm4(uint32_t* r, uint32_t addr) {
    asm volatile("ldmatrix.sync.aligned.m8n8.x4.shared.b16 {%0,%1,%2,%3},[%4];"
                 : "=r"(r[0]), "=r"(r[1]), "=r"(r[2]), "=r"(r[3]) : "r"(addr));
}
__device__ __forceinline__ void ldsm4t(uint32_t* r, uint32_t addr) {
    asm volatile("ldmatrix.sync.aligned.m8n8.x4.trans.shared.b16 {%0,%1,%2,%3},[%4];"
                 : "=r"(r[0]), "=r"(r[1]), "=r"(r[2]), "=r"(r[3]) : "r"(addr));
}
__device__ __forceinline__ void mma16816(float* c, const uint32_t* a, const uint32_t* b) {
    asm volatile(
        "mma.sync.aligned.m16n8k16.row.col.f32.bf16.bf16.f32 "
        "{%0,%1,%2,%3},{%4,%5,%6,%7},{%8,%9},{%0,%1,%2,%3};"
        : "+f"(c[0]), "+f"(c[1]), "+f"(c[2]), "+f"(c[3])
        : "r"(a[0]), "r"(a[1]), "r"(a[2]), "r"(a[3]), "r"(b[0]), "r"(b[1]));
}
union BF2U { __nv_bfloat162 h; uint32_t u; };
// split (x,y) into hi/lo bf16x2 packed u32 (x in low half)
__device__ __forceinline__ void split2(float x, float y, uint32_t& hi, uint32_t& lo) {
    BF2U H, L;
    H.h = __floats2bfloat162_rn(x, y);
    float rx = x - __low2float(H.h);
    float ry = y - __high2float(H.h);
    L.h = __floats2bfloat162_rn(rx, ry);
    hi = H.u; lo = L.u;
}

// ---------------------------------------------------------------------------
// GroupNorm (memory-bound)
// ---------------------------------------------------------------------------
__global__ __launch_bounds__(256) void gn_kernel(
    const float* __restrict__ x, const float* __restrict__ scale,
    const float* __restrict__ bias, float* __restrict__ xn) {
    int blk = blockIdx.x;
    int b = blk >> 5, g = blk & 31;
    const float4* xp4 = (const float4*)(x + ((size_t)b * CC + (size_t)g * CPG) * TT);
    float4* xnp4 = (float4*)(xn + ((size_t)b * CC + (size_t)g * CPG) * TT);
    const int N4 = CPG * TT / 4;

    float s = 0.f, ss = 0.f;
    for (int i = threadIdx.x; i < N4; i += 256) {
        float4 v = xp4[i];
        s += v.x + v.y + v.z + v.w;
        ss += v.x * v.x + v.y * v.y + v.z * v.z + v.w * v.w;
    }
    for (int o = 16; o; o >>= 1) {
        s += __shfl_down_sync(0xffffffffu, s, o);
        ss += __shfl_down_sync(0xffffffffu, ss, o);
    }
    __shared__ float red0[8], red1[8];
    __shared__ float mean_s, inv_s;
    int warp = threadIdx.x >> 5, lane = threadIdx.x & 31;
    if (lane == 0) { red0[warp] = s; red1[warp] = ss; }
    __syncthreads();
    if (threadIdx.x == 0) {
        float S = 0.f, SS = 0.f;
        #pragma unroll
        for (int w = 0; w < 8; w++) { S += red0[w]; SS += red1[w]; }
        const float invn = 1.f / (float)(CPG * TT);
        float mean = S * invn;
        float var = SS * invn - mean * mean;
        mean_s = mean;
        inv_s = rsqrtf(var + 1e-5f);
    }
    __syncthreads();
    float mean = mean_s, inv = inv_s;
    for (int i = threadIdx.x; i < N4; i += 256) {
        int ch = g * CPG + (i >> 8);
        float sc = scale[ch] * inv, bi = bias[ch] - mean * sc;
        float4 v = xp4[i];
        v.x = v.x * sc + bi; v.y = v.y * sc + bi;
        v.z = v.z * sc + bi; v.w = v.w * sc + bi;
        xnp4[i] = v;
    }
}

// ---------------------------------------------------------------------------
// GEMM via mma.sync bf16 split-3: out[b](MxN)=W@X[b]+bias(+res). N=1024.
// Block 128m x 64n, 8 warps (4m x 2n), warp 32x32. K-step 16, double buffer.
// ---------------------------------------------------------------------------
__global__ __launch_bounds__(256, 2) void gemm_mma(
    const float* __restrict__ W, const float* __restrict__ X,
    const float* __restrict__ bias, const float* __restrict__ res,
    float* __restrict__ out, int M, int K) {
    const int N = TT;
    int bb = blockIdx.z;
    const float* Xb = X + (size_t)bb * K * N;
    float* Ob = out + (size_t)bb * M * N;
    const float* Rb = res ? res + (size_t)bb * M * N : nullptr;

    // [buf][side(hi/lo)][...]
    __shared__ __align__(16) __nv_bfloat16 sA[2][2][128][24];  // [m][k] row-major
    __shared__ __align__(16) __nv_bfloat16 sB[2][2][16][72];   // [k][n]

    const uint32_t uA = cvta_smem(sA);
    const uint32_t uB = cvta_smem(sB);
    const int ABUF = 2 * 128 * 24 * 2, ASIDE = 128 * 24 * 2;
    const int BBUF = 2 * 16 * 72 * 2, BSIDE = 16 * 72 * 2;

    int tid = threadIdx.x, lane = tid & 31, warp = tid >> 5;
    int wm = warp >> 1, wn = warp & 1;
    int m0 = blockIdx.y * 128, n0 = blockIdx.x * 64;

    // global load indices
    int am = tid >> 2, akq = tid & 3;      // A: 2 float4 (rows am, am+64)
    int bk = tid >> 4, bn4 = tid & 15;     // B: 1 float4

    float4 ra0, ra1, rb0;
    const int NT = K / 16;

    auto gload = [&](int kt) {
        ra0 = *(const float4*)&W[(size_t)(m0 + am) * K + kt * 16 + akq * 4];
        ra1 = *(const float4*)&W[(size_t)(m0 + am + 64) * K + kt * 16 + akq * 4];
        rb0 = *(const float4*)&Xb[(size_t)(kt * 16 + bk) * N + n0 + bn4 * 4];
    };
    auto sstore = [&](int buf) {
        uint32_t h0, l0, h1, l1;
        split2(ra0.x, ra0.y, h0, l0); split2(ra0.z, ra0.w, h1, l1);
        *(uint2*)&sA[buf][0][am][akq * 4] = make_uint2(h0, h1);
        *(uint2*)&sA[buf][1][am][akq * 4] = make_uint2(l0, l1);
        split2(ra1.x, ra1.y, h0, l0); split2(ra1.z, ra1.w, h1, l1);
        *(uint2*)&sA[buf][0][am + 64][akq * 4] = make_uint2(h0, h1);
        *(uint2*)&sA[buf][1][am + 64][akq * 4] = make_uint2(l0, l1);
        split2(rb0.x, rb0.y, h0, l0); split2(rb0.z, rb0.w, h1, l1);
        *(uint2*)&sB[buf][0][bk][bn4 * 4] = make_uint2(h0, h1);
        *(uint2*)&sB[buf][1][bk][bn4 * 4] = make_uint2(l0, l1);
    };

    // ldmatrix lane offsets
    uint32_t aoff[2], boff[2];
    {
        int arow = lane & 15, acol = (lane & 16) ? 8 : 0;
        #pragma unroll
        for (int mt = 0; mt < 2; mt++)
            aoff[mt] = ((wm * 32 + mt * 16 + arow) * 24 + acol) * 2;
        int bkr = lane & 15, bnc = (lane & 16) ? 8 : 0;
        #pragma unroll
        for (int h = 0; h < 2; h++)
            boff[h] = (bkr * 72 + wn * 32 + h * 16 + bnc) * 2;
    }

    float c[2][4][4];
    #pragma unroll
    for (int i = 0; i < 2; i++)
        #pragma unroll
        for (int j = 0; j < 4; j++)
            #pragma unroll
            for (int k = 0; k < 4; k++) c[i][j][k] = 0.f;

    gload(0);
    sstore(0);
    __syncthreads();

    for (int kt = 0; kt < NT; kt++) {
        int cur = kt & 1;
        if (kt + 1 < NT) gload(kt + 1);
        uint32_t aB = uA + cur * ABUF;
        uint32_t bB = uB + cur * BBUF;
        uint32_t ah[2][4], al[2][4], bh[2][4], bl[2][4];
        #pragma unroll
        for (int mt = 0; mt < 2; mt++) {
            ldsm4(ah[mt], aB + aoff[mt]);
            ldsm4(al[mt], aB + ASIDE + aoff[mt]);
        }
        #pragma unroll
        for (int h = 0; h < 2; h++) {
            ldsm4t(bh[h], bB + boff[h]);
            ldsm4t(bl[h], bB + BSIDE + boff[h]);
        }
        #pragma unroll
        for (int mt = 0; mt < 2; mt++)
            #pragma unroll
            for (int nt = 0; nt < 4; nt++) {
                uint32_t* B_h = &bh[nt >> 1][(nt & 1) * 2];
                uint32_t* B_l = &bl[nt >> 1][(nt & 1) * 2];
                mma16816(c[mt][nt], ah[mt], B_h);
                mma16816(c[mt][nt], al[mt], B_h);
                mma16816(c[mt][nt], ah[mt], B_l);
            }
        if (kt + 1 < NT) {
            sstore((kt + 1) & 1);
            __syncthreads();
        }
    }

    // epilogue
    #pragma unroll
    for (int mt = 0; mt < 2; mt++) {
        int r0 = m0 + wm * 32 + mt * 16 + (lane >> 2);
        int r1 = r0 + 8;
        float b0v = bias[r0], b1v = bias[r1];
        #pragma unroll
        for (int nt = 0; nt < 4; nt++) {
            int cc = n0 + wn * 32 + nt * 8 + (lane & 3) * 2;
            float2 v0 = {c[mt][nt][0] + b0v, c[mt][nt][1] + b0v};
            float2 v1 = {c[mt][nt][2] + b1v, c[mt][nt][3] + b1v};
            if (Rb) {
                float2 q0 = *(const float2*)&Rb[(size_t)r0 * N + cc];
                float2 q1 = *(const float2*)&Rb[(size_t)r1 * N + cc];
                v0.x += q0.x; v0.y += q0.y; v1.x += q1.x; v1.y += q1.y;
            }
            *(float2*)&Ob[(size_t)r0 * N + cc] = v0;
            *(float2*)&Ob[(size_t)r1 * N + cc] = v1;
        }
    }
}

// ---------------------------------------------------------------------------
// Attention via mma: block = (head, 64-query tile). K/V tiles of 64 keys.
// QK: A=Q (trans-ldsm from [c][q]), B=K (trans from [c][s]).
// PV: A=P ([q][s] row-major), B=V (non-trans from [c][s]).
// ---------------------------------------------------------------------------
#define SQ_BYTES (2 * 64 * 72 * 2)   // per tensor: 2 sides
#define O_Q 0
#define O_K (O_Q + SQ_BYTES)
#define O_V (O_K + SQ_BYTES)
#define O_P (O_V + SQ_BYTES)
#define O_S (O_P + SQ_BYTES)             // f32 [64][68]
#define O_M (O_S + 64 * 68 * 4)
#define O_L (O_M + 256)
#define O_AL (O_L + 256)
#define ATTN_SMEM (O_AL + 256)

__global__ __launch_bounds__(256) void attn_mma(
    const float* __restrict__ qkv, float* __restrict__ attn) {
    extern __shared__ char smem[];
    __nv_bfloat16* sQ = (__nv_bfloat16*)(smem + O_Q);  // [side][c=64][72]
    __nv_bfloat16* sK = (__nv_bfloat16*)(smem + O_K);  // [side][c][s]
    __nv_bfloat16* sV = (__nv_bfloat16*)(smem + O_V);  // [side][c][s]
    __nv_bfloat16* sP = (__nv_bfloat16*)(smem + O_P);  // [side][q][s]
    float* sS = (float*)(smem + O_S);                  // [64][68]
    float* m_s = (float*)(smem + O_M);
    float* l_s = (float*)(smem + O_L);
    float* al_s = (float*)(smem + O_AL);
    const int SIDE = 64 * 72;  // elements per side

    const uint32_t uQ = cvta_smem(sQ), uK = cvta_smem(sK);
    const uint32_t uV = cvta_smem(sV), uP = cvta_smem(sP);
    const uint32_t SIDEB = SIDE * 2;

    int tid = threadIdx.x, lane = tid & 31, warp = tid >> 5;
    int wq = warp >> 1, ws = warp & 1;
    int qbase = wq * 16, sbase = ws * 32;
    int head = blockIdx.y;
    int b = head >> 3, hd = head & 7;
    int q0g = blockIdx.x * 64;

    const float* qp = qkv + ((size_t)b * 3 * CC + (size_t)hd * 192) * TT;
    const float* kp = qp + (size_t)64 * TT;
    const float* vp = kp + (size_t)64 * TT;

    // load Q once: [c][q], natural layout
    #pragma unroll
    for (int it = 0; it < 4; it++) {
        int e = tid + it * 256;
        int cch = e >> 4, q4 = e & 15;
        float4 v = *(const float4*)&qp[(size_t)cch * TT + q0g + q4 * 4];
        uint32_t h0, l0, h1, l1;
        split2(v.x, v.y, h0, l0); split2(v.z, v.w, h1, l1);
        *(uint2*)&sQ[cch * 72 + q4 * 4] = make_uint2(h0, h1);
        *(uint2*)&sQ[SIDE + cch * 72 + q4 * 4] = make_uint2(l0, l1);
    }
    if (tid < 64) { m_s[tid] = -1e30f; l_s[tid] = 0.f; }

    float o[4][4];
    #pragma unroll
    for (int i = 0; i < 4; i++)
        #pragma unroll
        for (int j = 0; j < 4; j++) o[i][j] = 0.f;

    // lane offsets
    // QK A (Q, trans): c row, q 16B segment
    uint32_t qk_a_off = (((lane & 7) + ((lane & 16) ? 8 : 0)) * 72 +
                         qbase + ((lane & 8) ? 8 : 0)) * 2;
    // QK B (K, trans): c row (lane&15), s segment
    uint32_t qk_b_off[2];
    #pragma unroll
    for (int h = 0; h < 2; h++)
        qk_b_off[h] = ((lane & 15) * 72 + sbase + h * 16 + ((lane & 16) ? 8 : 0)) * 2;
    // PV A (P, non-trans): q row (lane&15), s segment
    uint32_t pv_a_off = ((qbase + (lane & 15)) * 72 + ((lane & 16) ? 8 : 0)) * 2;
    // PV B (V, non-trans): c row, s segment
    uint32_t pv_b_off[2];
    #pragma unroll
    for (int h = 0; h < 2; h++)
        pv_b_off[h] = ((ws * 32 + h * 16 + (lane & 7) + ((lane & 16) ? 8 : 0)) * 72 +
                       ((lane & 8) ? 8 : 0)) * 2;
    __syncthreads();

    for (int kt = 0; kt < TT / 64; kt++) {
        int s0g = kt * 64;
        // load K,V tile
        #pragma unroll
        for (int it = 0; it < 4; it++) {
            int e = tid + it * 256;
            int cch = e >> 4, s4 = e & 15;
            float4 kv = *(const float4*)&kp[(size_t)cch * TT + s0g + s4 * 4];
            float4 vv = *(const float4*)&vp[(size_t)cch * TT + s0g + s4 * 4];
            uint32_t h0, l0, h1, l1;
            split2(kv.x, kv.y, h0, l0); split2(kv.z, kv.w, h1, l1);
            *(uint2*)&sK[cch * 72 + s4 * 4] = make_uint2(h0, h1);
            *(uint2*)&sK[SIDE + cch * 72 + s4 * 4] = make_uint2(l0, l1);
            split2(vv.x, vv.y, h0, l0); split2(vv.z, vv.w, h1, l1);
            *(uint2*)&sV[cch * 72 + s4 * 4] = make_uint2(h0, h1);
            *(uint2*)&sV[SIDE + cch * 72 + s4 * 4] = make_uint2(l0, l1);
        }
        __syncthreads();

        // ---- QK ----
        {
            float sc[4][4];
            #pragma unroll
            for (int i = 0; i < 4; i++)
                #pragma unroll
                for (int j = 0; j < 4; j++) sc[i][j] = 0.f;
            #pragma unroll
            for (int cs = 0; cs < 4; cs++) {
                uint32_t coff = cs * 16 * 72 * 2;
                uint32_t ah[4], al[4], bh[2][4], bl[2][4];
                ldsm4t(ah, uQ + qk_a_off + coff);
                ldsm4t(al, uQ + SIDEB + qk_a_off + coff);
                #pragma unroll
                for (int h = 0; h < 2; h++) {
                    ldsm4t(bh[h], uK + qk_b_off[h] + coff);
                    ldsm4t(bl[h], uK + SIDEB + qk_b_off[h] + coff);
                }
                #pragma unroll
                for (int nt = 0; nt < 4; nt++) {
                    uint32_t* B_h = &bh[nt >> 1][(nt & 1) * 2];
                    uint32_t* B_l = &bl[nt >> 1][(nt & 1) * 2];
                    mma16816(sc[nt], ah, B_h);
                    mma16816(sc[nt], al, B_h);
                    mma16816(sc[nt], ah, B_l);
                }
            }
            int r0 = qbase + (lane >> 2);
            #pragma unroll
            for (int nt = 0; nt < 4; nt++) {
                int cc = sbase + nt * 8 + (lane & 3) * 2;
                *(float2*)&sS[r0 * 68 + cc] =
                    make_float2(sc[nt][0] * 0.125f, sc[nt][1] * 0.125f);
                *(float2*)&sS[(r0 + 8) * 68 + cc] =
                    make_float2(sc[nt][2] * 0.125f, sc[nt][3] * 0.125f);
            }
        }
        __syncthreads();

        // ---- softmax: 4 threads per row, write P hi/lo ----
        {
            int q = tid >> 2, part = tid & 3;
            float pv[16];
            #pragma unroll
            for (int j4 = 0; j4 < 4; j4++)
                *(float4*)&pv[j4 * 4] = *(const float4*)&sS[q * 68 + part * 16 + j4 * 4];
            float mprev = m_s[q];
            float mx = -1e30f;
            #pragma unroll
            for (int j = 0; j < 16; j++) mx = fmaxf(mx, pv[j]);
            mx = fmaxf(mx, __shfl_xor_sync(0xffffffffu, mx, 1));
            mx = fmaxf(mx, __shfl_xor_sync(0xffffffffu, mx, 2));
            mx = fmaxf(mx, mprev);
            float sum = 0.f;
            #pragma unroll
            for (int j = 0; j < 16; j++) { pv[j] = __expf(pv[j] - mx); sum += pv[j]; }
            sum += __shfl_xor_sync(0xffffffffu, sum, 1);
            sum += __shfl_xor_sync(0xffffffffu, sum, 2);
            #pragma unroll
            for (int j4 = 0; j4 < 4; j4++) {
                uint32_t h0, l0, h1, l1;
                split2(pv[j4 * 4], pv[j4 * 4 + 1], h0, l0);
                split2(pv[j4 * 4 + 2], pv[j4 * 4 + 3], h1, l1);
                *(uint2*)&sP[q * 72 + part * 16 + j4 * 4] = make_uint2(h0, h1);
                *(uint2*)&sP[SIDE + q * 72 + part * 16 + j4 * 4] = make_uint2(l0, l1);
            }
            if (part == 0) {
                float al = __expf(mprev - mx);
                m_s[q] = mx;
                al_s[q] = al;
                l_s[q] = l_s[q] * al + sum;
            }
        }
        __syncthreads();

        // ---- PV ----
        {
            float al0 = al_s[qbase + (lane >> 2)];
            float al1 = al_s[qbase + (lane >> 2) + 8];
            #pragma unroll
            for (int nt = 0; nt < 4; nt++) {
                o[nt][0] *= al0; o[nt][1] *= al0;
                o[nt][2] *= al1; o[nt][3] *= al1;
            }
            #pragma unroll
            for (int st = 0; st < 4; st++) {
                uint32_t soff = st * 16 * 2;  // s advances along row (contig)
                uint32_t ah[4], al_[4], bh[2][4], bl[2][4];
                ldsm4(ah, uP + pv_a_off + soff);
                ldsm4(al_, uP + SIDEB + pv_a_off + soff);
                #pragma unroll
                for (int h = 0; h < 2; h++) {
                    ldsm4(bh[h], uV + pv_b_off[h] + soff);
                    ldsm4(bl[h], uV + SIDEB + pv_b_off[h] + soff);
                }
                #pragma unroll
                for (int nt = 0; nt < 4; nt++) {
                    uint32_t* B_h = &bh[nt >> 1][(nt & 1) * 2];
                    uint32_t* B_l = &bl[nt >> 1][(nt & 1) * 2];
                    mma16816(o[nt], ah, B_h);
                    mma16816(o[nt], al_, B_h);
                    mma16816(o[nt], ah, B_l);
                }
            }
        }
        __syncthreads();
    }

    // normalize + stage [c][q] in sS, then coalesced store
    {
        float li0 = 1.f / l_s[qbase + (lane >> 2)];
        float li1 = 1.f / l_s[qbase + (lane >> 2) + 8];
        int qq = qbase + (lane >> 2);
        #pragma unroll
        for (int nt = 0; nt < 4; nt++) {
            int c0 = ws * 32 + nt * 8 + (lane & 3) * 2;
            sS[c0 * 68 + qq] = o[nt][0] * li0;
            sS[(c0 + 1) * 68 + qq] = o[nt][1] * li0;
            sS[c0 * 68 + qq + 8] = o[nt][2] * li1;
            sS[(c0 + 1) * 68 + qq + 8] = o[nt][3] * li1;
        }
    }
    __syncthreads();
    float* op = attn + ((size_t)b * CC + (size_t)hd * 64) * TT + q0g;
    #pragma unroll
    for (int it = 0; it < 4; it++) {
        int e = tid + it * 256;
        int cch = e >> 4, q4 = e & 15;
        *(float4*)&op[(size_t)cch * TT + q4 * 4] = *(const float4*)&sS[cch * 68 + q4 * 4];
    }
}

// ---------------------------------------------------------------------------
extern "C" void kernel_launch(void* const* d_in, const int* in_sizes, int n_in,
                              void* d_out, int out_size) {
    const float* x = (const float*)d_in[0];
    const float* gn_scale = (const float*)d_in[1];
    const float* gn_bias = (const float*)d_in[2];
    const float* w_qkv = (const float*)d_in[3];
    const float* b_qkv = (const float*)d_in[4];
    const float* w_proj = (const float*)d_in[5];
    const float* b_proj = (const float*)d_in[6];
    float* out = (float*)d_out;

    float *xn, *qkv, *attn;
    cudaGetSymbolAddress((void**)&xn, g_xn);
    cudaGetSymbolAddress((void**)&qkv, g_qkv);
    cudaGetSymbolAddress((void**)&attn, g_attn);

    cudaFuncSetAttribute(attn_mma, cudaFuncAttributeMaxDynamicSharedMemorySize,
                         ATTN_SMEM);

    gn_kernel<<<BB * NG, 256>>>(x, gn_scale, gn_bias, xn);
    gemm_mma<<<dim3(TT / 64, (3 * CC) / 128, BB), 256>>>(
        w_qkv, xn, b_qkv, nullptr, qkv, 3 * CC, CC);
    attn_mma<<<dim3(TT / 64, BB * NH), 256, ATTN_SMEM>>>(qkv, attn);
    gemm_mma<<<dim3(TT / 64, CC / 128, BB), 256>>>(
        w_proj, attn, b_proj, x, out, CC, CC);
}

// round 8
// speedup vs baseline: 2.7853x; 1.1096x over previous
#include <cuda_runtime.h>
#include <cuda_bf16.h>
#include <cstdint>

#define BB 16
#define CC 512
#define TT 1024
#define NH 8
#define DH 64
#define NG 32
#define CPG 16

typedef __nv_bfloat16 bf16;

// ---------------- scratch: all intermediates as bf16 hi/lo planes ----------
__device__ bf16 g_xn_h[BB * CC * TT];
__device__ bf16 g_xn_l[BB * CC * TT];
__device__ bf16 g_qkv_h[BB * 3 * CC * TT];
__device__ bf16 g_qkv_l[BB * 3 * CC * TT];
__device__ bf16 g_at_h[BB * CC * TT];
__device__ bf16 g_at_l[BB * CC * TT];

// ---------------- helpers ----------------
__device__ __forceinline__ uint32_t cvta_smem(const void* p) {
    uint32_t a;
    asm("{.reg .u64 t; cvta.to.shared.u64 t, %1; cvt.u32.u64 %0, t;}"
        : "=r"(a) : "l"(p));
    return a;
}
__device__ __forceinline__ void ldsm4(uint32_t* r, uint32_t addr) {
    asm volatile("ldmatrix.sync.aligned.m8n8.x4.shared.b16 {%0,%1,%2,%3},[%4];"
                 : "=r"(r[0]), "=r"(r[1]), "=r"(r[2]), "=r"(r[3]) : "r"(addr));
}
__device__ __forceinline__ void ldsm4t(uint32_t* r, uint32_t addr) {
    asm volatile("ldmatrix.sync.aligned.m8n8.x4.trans.shared.b16 {%0,%1,%2,%3},[%4];"
                 : "=r"(r[0]), "=r"(r[1]), "=r"(r[2]), "=r"(r[3]) : "r"(addr));
}
__device__ __forceinline__ void mma16816(float* c, const uint32_t* a, const uint32_t* b) {
    asm volatile(
        "mma.sync.aligned.m16n8k16.row.col.f32.bf16.bf16.f32 "
        "{%0,%1,%2,%3},{%4,%5,%6,%7},{%8,%9},{%0,%1,%2,%3};"
        : "+f"(c[0]), "+f"(c[1]), "+f"(c[2]), "+f"(c[3])
        : "r"(a[0]), "r"(a[1]), "r"(a[2]), "r"(a[3]), "r"(b[0]), "r"(b[1]));
}
__device__ __forceinline__ void cpa16(uint32_t dst, const void* src) {
    asm volatile("cp.async.cg.shared.global [%0],[%1],16;" :: "r"(dst), "l"(src));
}
__device__ __forceinline__ void cpa_commit() {
    asm volatile("cp.async.commit_group;");
}
__device__ __forceinline__ void cpa_wait0() {
    asm volatile("cp.async.wait_group 0;");
}
union BF2U { __nv_bfloat162 h; uint32_t u; };
__device__ __forceinline__ void split2(float x, float y, uint32_t& hi, uint32_t& lo) {
    BF2U H, L;
    H.h = __floats2bfloat162_rn(x, y);
    float rx = x - __low2float(H.h);
    float ry = y - __high2float(H.h);
    L.h = __floats2bfloat162_rn(rx, ry);
    hi = H.u; lo = L.u;
}

// ---------------------------------------------------------------------------
// GroupNorm -> bf16 hi/lo planes
// ---------------------------------------------------------------------------
__global__ __launch_bounds__(256) void gn_kernel(
    const float* __restrict__ x, const float* __restrict__ scale,
    const float* __restrict__ bias, bf16* __restrict__ xnh,
    bf16* __restrict__ xnl) {
    int blk = blockIdx.x;
    int b = blk >> 5, g = blk & 31;
    size_t base = ((size_t)b * CC + (size_t)g * CPG) * TT;
    const float4* xp4 = (const float4*)(x + base);
    const int N4 = CPG * TT / 4;

    float s = 0.f, ss = 0.f;
    for (int i = threadIdx.x; i < N4; i += 256) {
        float4 v = xp4[i];
        s += v.x + v.y + v.z + v.w;
        ss += v.x * v.x + v.y * v.y + v.z * v.z + v.w * v.w;
    }
    for (int o = 16; o; o >>= 1) {
        s += __shfl_down_sync(0xffffffffu, s, o);
        ss += __shfl_down_sync(0xffffffffu, ss, o);
    }
    __shared__ float red0[8], red1[8];
    __shared__ float mean_s, inv_s;
    int warp = threadIdx.x >> 5, lane = threadIdx.x & 31;
    if (lane == 0) { red0[warp] = s; red1[warp] = ss; }
    __syncthreads();
    if (threadIdx.x == 0) {
        float S = 0.f, SS = 0.f;
        #pragma unroll
        for (int w = 0; w < 8; w++) { S += red0[w]; SS += red1[w]; }
        const float invn = 1.f / (float)(CPG * TT);
        float mean = S * invn;
        float var = SS * invn - mean * mean;
        mean_s = mean;
        inv_s = rsqrtf(var + 1e-5f);
    }
    __syncthreads();
    float mean = mean_s, inv = inv_s;
    for (int i = threadIdx.x; i < N4; i += 256) {
        int ch = g * CPG + (i >> 8);
        float sc = scale[ch] * inv, bi = bias[ch] - mean * sc;
        float4 v = xp4[i];
        v.x = v.x * sc + bi; v.y = v.y * sc + bi;
        v.z = v.z * sc + bi; v.w = v.w * sc + bi;
        uint32_t h0, l0, h1, l1;
        split2(v.x, v.y, h0, l0); split2(v.z, v.w, h1, l1);
        *(uint2*)&xnh[base + (size_t)i * 4] = make_uint2(h0, h1);
        *(uint2*)&xnl[base + (size_t)i * 4] = make_uint2(l0, l1);
    }
}

// ---------------------------------------------------------------------------
// GEMM: out[b](MxN)=W@X[b]+bias(+res). X given as bf16 hi/lo planes.
// Block 128x128, 8 warps (2m x 4n), warp 64x32. K-step 16, double buffer,
// cp.async for X tiles. PO: write bf16 planes; else f32 (+residual).
// ---------------------------------------------------------------------------
template <bool PO>
__global__ __launch_bounds__(256, 2) void gemm_mma(
    const float* __restrict__ W, const bf16* __restrict__ Xh,
    const bf16* __restrict__ Xl, const float* __restrict__ bias,
    const float* __restrict__ res, float* __restrict__ outf,
    bf16* __restrict__ oh, bf16* __restrict__ ol, int M, int K) {
    const int N = TT;
    int bb = blockIdx.z;
    size_t xoff = (size_t)bb * K * N;

    __shared__ __align__(16) bf16 sA[2][2][128][24];   // [buf][side][m][k]
    __shared__ __align__(16) bf16 sB[2][2][16][136];   // [buf][side][k][n]

    const uint32_t uA = cvta_smem(sA);
    const uint32_t uB = cvta_smem(sB);

    int tid = threadIdx.x, lane = tid & 31, warp = tid >> 5;
    int wm = warp >> 2, wn = warp & 3;
    int m0 = blockIdx.y * 128, n0 = blockIdx.x * 128;

    int am = tid >> 2, akq = tid & 3;   // W: rows am, am+64
    int brow = tid >> 4, bc16 = tid & 15;

    float4 ra0, ra1;
    const int NT = K / 16;

    auto gloadW = [&](int kt) {
        ra0 = *(const float4*)&W[(size_t)(m0 + am) * K + kt * 16 + akq * 4];
        ra1 = *(const float4*)&W[(size_t)(m0 + am + 64) * K + kt * 16 + akq * 4];
    };
    auto sstoreW = [&](int buf) {
        uint32_t h0, l0, h1, l1;
        split2(ra0.x, ra0.y, h0, l0); split2(ra0.z, ra0.w, h1, l1);
        *(uint2*)&sA[buf][0][am][akq * 4] = make_uint2(h0, h1);
        *(uint2*)&sA[buf][1][am][akq * 4] = make_uint2(l0, l1);
        split2(ra1.x, ra1.y, h0, l0); split2(ra1.z, ra1.w, h1, l1);
        *(uint2*)&sA[buf][0][am + 64][akq * 4] = make_uint2(h0, h1);
        *(uint2*)&sA[buf][1][am + 64][akq * 4] = make_uint2(l0, l1);
    };
    auto cpB = [&](int kt, int buf) {
        size_t src = xoff + (size_t)(kt * 16 + brow) * N + n0 + bc16 * 8;
        uint32_t d0 = uB + (uint32_t)(((buf * 2 + 0) * 16 + brow) * 136 + bc16 * 8) * 2;
        uint32_t d1 = uB + (uint32_t)(((buf * 2 + 1) * 16 + brow) * 136 + bc16 * 8) * 2;
        cpa16(d0, Xh + src);
        cpa16(d1, Xl + src);
    };

    // ldmatrix lane offsets
    uint32_t aoff[4], boff[2];
    {
        int arow = lane & 15, acol = (lane & 16) ? 8 : 0;
        #pragma unroll
        for (int mt = 0; mt < 4; mt++)
            aoff[mt] = ((wm * 64 + mt * 16 + arow) * 24 + acol) * 2;
        int bkr = lane & 15, bnc = (lane & 16) ? 8 : 0;
        #pragma unroll
        for (int h = 0; h < 2; h++)
            boff[h] = (bkr * 136 + wn * 32 + h * 16 + bnc) * 2;
    }

    float c[4][4][4];
    #pragma unroll
    for (int i = 0; i < 4; i++)
        #pragma unroll
        for (int j = 0; j < 4; j++)
            #pragma unroll
            for (int k = 0; k < 4; k++) c[i][j][k] = 0.f;

    cpB(0, 0);
    cpa_commit();
    gloadW(0);
    sstoreW(0);
    cpa_wait0();
    __syncthreads();

    const uint32_t ABUF = 2 * 128 * 24 * 2, ASIDE = 128 * 24 * 2;
    const uint32_t BBUF = 2 * 16 * 136 * 2, BSIDE = 16 * 136 * 2;

    for (int kt = 0; kt < NT; kt++) {
        int cur = kt & 1;
        if (kt + 1 < NT) {
            gloadW(kt + 1);
            cpB(kt + 1, cur ^ 1);
            cpa_commit();
        }
        uint32_t aB = uA + cur * ABUF;
        uint32_t bB = uB + cur * BBUF;
        uint32_t bh[2][4], bl[2][4];
        #pragma unroll
        for (int h = 0; h < 2; h++) {
            ldsm4t(bh[h], bB + boff[h]);
            ldsm4t(bl[h], bB + BSIDE + boff[h]);
        }
        #pragma unroll
        for (int mt = 0; mt < 4; mt++) {
            uint32_t ah[4], al[4];
            ldsm4(ah, aB + aoff[mt]);
            ldsm4(al, aB + ASIDE + aoff[mt]);
            #pragma unroll
            for (int nt = 0; nt < 4; nt++) {
                uint32_t* B_h = &bh[nt >> 1][(nt & 1) * 2];
                uint32_t* B_l = &bl[nt >> 1][(nt & 1) * 2];
                mma16816(c[mt][nt], ah, B_h);
                mma16816(c[mt][nt], al, B_h);
                mma16816(c[mt][nt], ah, B_l);
            }
        }
        if (kt + 1 < NT) {
            sstoreW(cur ^ 1);
            cpa_wait0();
            __syncthreads();
        }
    }

    // epilogue
    #pragma unroll
    for (int mt = 0; mt < 4; mt++) {
        int r0 = m0 + wm * 64 + mt * 16 + (lane >> 2);
        int r1 = r0 + 8;
        float b0v = bias[r0], b1v = bias[r1];
        #pragma unroll
        for (int nt = 0; nt < 4; nt++) {
            int cc = n0 + wn * 32 + nt * 8 + (lane & 3) * 2;
            float v00 = c[mt][nt][0] + b0v, v01 = c[mt][nt][1] + b0v;
            float v10 = c[mt][nt][2] + b1v, v11 = c[mt][nt][3] + b1v;
            size_t i0 = (size_t)bb * M * N + (size_t)r0 * N + cc;
            size_t i1 = (size_t)bb * M * N + (size_t)r1 * N + cc;
            if (PO) {
                uint32_t h, l;
                split2(v00, v01, h, l);
                *(uint32_t*)&oh[i0] = h; *(uint32_t*)&ol[i0] = l;
                split2(v10, v11, h, l);
                *(uint32_t*)&oh[i1] = h; *(uint32_t*)&ol[i1] = l;
            } else {
                float2 v0 = {v00, v01}, v1 = {v10, v11};
                if (res) {
                    float2 q0 = *(const float2*)&res[i0];
                    float2 q1 = *(const float2*)&res[i1];
                    v0.x += q0.x; v0.y += q0.y; v1.x += q1.x; v1.y += q1.y;
                }
                *(float2*)&outf[i0] = v0;
                *(float2*)&outf[i1] = v1;
            }
        }
    }
}

// ---------------------------------------------------------------------------
// Attention: block = (head, 64-query tile). Q/K/V loaded from bf16 planes
// via cp.async; Q fragments hoisted into registers; P split in-kernel.
// ---------------------------------------------------------------------------
#define SQ_BYTES (2 * 64 * 72 * 2)
#define O_Q 0
#define O_K (O_Q + SQ_BYTES)
#define O_V (O_K + SQ_BYTES)
#define O_P (O_V + SQ_BYTES)
#define O_S (O_P + SQ_BYTES)
#define O_M (O_S + 64 * 68 * 4)
#define O_L (O_M + 256)
#define O_AL (O_L + 256)
#define ATTN_SMEM (O_AL + 256)

__global__ __launch_bounds__(256) void attn_mma(
    const bf16* __restrict__ qkvh, const bf16* __restrict__ qkvl,
    bf16* __restrict__ ath, bf16* __restrict__ atl) {
    extern __shared__ char smem[];
    bf16* sP = (bf16*)(smem + O_P);
    float* sS = (float*)(smem + O_S);
    float* m_s = (float*)(smem + O_M);
    float* l_s = (float*)(smem + O_L);
    float* al_s = (float*)(smem + O_AL);
    const int SIDE = 64 * 72;
    const uint32_t SIDEB = SIDE * 2;

    const uint32_t uQ = cvta_smem(smem + O_Q);
    const uint32_t uK = cvta_smem(smem + O_K);
    const uint32_t uV = cvta_smem(smem + O_V);
    const uint32_t uP = cvta_smem(sP);

    int tid = threadIdx.x, lane = tid & 31, warp = tid >> 5;
    int wq = warp >> 1, ws = warp & 1;
    int qbase = wq * 16, sbase = ws * 32;
    int head = blockIdx.y;
    int b = head >> 3, hd = head & 7;
    int q0g = blockIdx.x * 64;

    size_t hoff = ((size_t)b * 3 * CC + (size_t)hd * 192) * TT;
    const bf16* qph = qkvh + hoff;
    const bf16* qpl = qkvl + hoff;
    const bf16* kph = qph + (size_t)64 * TT;
    const bf16* kpl = qpl + (size_t)64 * TT;
    const bf16* vph = kph + (size_t)64 * TT;
    const bf16* vpl = kpl + (size_t)64 * TT;

    // chunk mapping: per plane 64 rows x 8 x 16B
    int crow[2], cc16[2];
    #pragma unroll
    for (int it = 0; it < 2; it++) {
        int e = tid + it * 256;
        crow[it] = e >> 3;
        cc16[it] = e & 7;
    }

    // load Q (both planes)
    #pragma unroll
    for (int it = 0; it < 2; it++) {
        uint32_t doff = (uint32_t)(crow[it] * 72 + cc16[it] * 8) * 2;
        size_t soff = (size_t)crow[it] * TT + q0g + cc16[it] * 8;
        cpa16(uQ + doff, qph + soff);
        cpa16(uQ + SIDEB + doff, qpl + soff);
    }
    cpa_commit();
    if (tid < 64) { m_s[tid] = -1e30f; l_s[tid] = 0.f; }

    float o[4][4];
    #pragma unroll
    for (int i = 0; i < 4; i++)
        #pragma unroll
        for (int j = 0; j < 4; j++) o[i][j] = 0.f;

    uint32_t qk_a_off = (((lane & 7) + ((lane & 16) ? 8 : 0)) * 72 +
                         qbase + ((lane & 8) ? 8 : 0)) * 2;
    uint32_t qk_b_off[2];
    #pragma unroll
    for (int h = 0; h < 2; h++)
        qk_b_off[h] = ((lane & 15) * 72 + sbase + h * 16 + ((lane & 16) ? 8 : 0)) * 2;
    uint32_t pv_a_off = ((qbase + (lane & 15)) * 72 + ((lane & 16) ? 8 : 0)) * 2;
    uint32_t pv_b_off[2];
    #pragma unroll
    for (int h = 0; h < 2; h++)
        pv_b_off[h] = ((ws * 32 + h * 16 + (lane & 7) + ((lane & 16) ? 8 : 0)) * 72 +
                       ((lane & 8) ? 8 : 0)) * 2;

    cpa_wait0();
    __syncthreads();

    // hoist Q fragments (loop-invariant)
    uint32_t qh[4][4], ql[4][4];
    #pragma unroll
    for (int cs = 0; cs < 4; cs++) {
        uint32_t coff = cs * 16 * 72 * 2;
        ldsm4t(qh[cs], uQ + qk_a_off + coff);
        ldsm4t(ql[cs], uQ + SIDEB + qk_a_off + coff);
    }

    for (int kt = 0; kt < TT / 64; kt++) {
        int s0g = kt * 64;
        // load K,V (both planes) via cp.async
        #pragma unroll
        for (int it = 0; it < 2; it++) {
            uint32_t doff = (uint32_t)(crow[it] * 72 + cc16[it] * 8) * 2;
            size_t soff = (size_t)crow[it] * TT + s0g + cc16[it] * 8;
            cpa16(uK + doff, kph + soff);
            cpa16(uK + SIDEB + doff, kpl + soff);
            cpa16(uV + doff, vph + soff);
            cpa16(uV + SIDEB + doff, vpl + soff);
        }
        cpa_commit();
        cpa_wait0();
        __syncthreads();

        // ---- QK ----
        {
            float sc[4][4];
            #pragma unroll
            for (int i = 0; i < 4; i++)
                #pragma unroll
                for (int j = 0; j < 4; j++) sc[i][j] = 0.f;
            #pragma unroll
            for (int cs = 0; cs < 4; cs++) {
                uint32_t coff = cs * 16 * 72 * 2;
                uint32_t bh[2][4], bl[2][4];
                #pragma unroll
                for (int h = 0; h < 2; h++) {
                    ldsm4t(bh[h], uK + qk_b_off[h] + coff);
                    ldsm4t(bl[h], uK + SIDEB + qk_b_off[h] + coff);
                }
                #pragma unroll
                for (int nt = 0; nt < 4; nt++) {
                    uint32_t* B_h = &bh[nt >> 1][(nt & 1) * 2];
                    uint32_t* B_l = &bl[nt >> 1][(nt & 1) * 2];
                    mma16816(sc[nt], qh[cs], B_h);
                    mma16816(sc[nt], ql[cs], B_h);
                    mma16816(sc[nt], qh[cs], B_l);
                }
            }
            int r0 = qbase + (lane >> 2);
            #pragma unroll
            for (int nt = 0; nt < 4; nt++) {
                int cc = sbase + nt * 8 + (lane & 3) * 2;
                *(float2*)&sS[r0 * 68 + cc] =
                    make_float2(sc[nt][0] * 0.125f, sc[nt][1] * 0.125f);
                *(float2*)&sS[(r0 + 8) * 68 + cc] =
                    make_float2(sc[nt][2] * 0.125f, sc[nt][3] * 0.125f);
            }
        }
        __syncthreads();

        // ---- softmax: 4 threads per row ----
        {
            int q = tid >> 2, part = tid & 3;
            float pv[16];
            #pragma unroll
            for (int j4 = 0; j4 < 4; j4++)
                *(float4*)&pv[j4 * 4] = *(const float4*)&sS[q * 68 + part * 16 + j4 * 4];
            float mprev = m_s[q];
            float mx = -1e30f;
            #pragma unroll
            for (int j = 0; j < 16; j++) mx = fmaxf(mx, pv[j]);
            mx = fmaxf(mx, __shfl_xor_sync(0xffffffffu, mx, 1));
            mx = fmaxf(mx, __shfl_xor_sync(0xffffffffu, mx, 2));
            mx = fmaxf(mx, mprev);
            float sum = 0.f;
            #pragma unroll
            for (int j = 0; j < 16; j++) { pv[j] = __expf(pv[j] - mx); sum += pv[j]; }
            sum += __shfl_xor_sync(0xffffffffu, sum, 1);
            sum += __shfl_xor_sync(0xffffffffu, sum, 2);
            #pragma unroll
            for (int j4 = 0; j4 < 4; j4++) {
                uint32_t h0, l0, h1, l1;
                split2(pv[j4 * 4], pv[j4 * 4 + 1], h0, l0);
                split2(pv[j4 * 4 + 2], pv[j4 * 4 + 3], h1, l1);
                *(uint2*)&sP[q * 72 + part * 16 + j4 * 4] = make_uint2(h0, h1);
                *(uint2*)&sP[SIDE + q * 72 + part * 16 + j4 * 4] = make_uint2(l0, l1);
            }
            if (part == 0) {
                float al = __expf(mprev - mx);
                m_s[q] = mx;
                al_s[q] = al;
                l_s[q] = l_s[q] * al + sum;
            }
        }
        __syncthreads();

        // ---- PV ----
        {
            float al0 = al_s[qbase + (lane >> 2)];
            float al1 = al_s[qbase + (lane >> 2) + 8];
            #pragma unroll
            for (int nt = 0; nt < 4; nt++) {
                o[nt][0] *= al0; o[nt][1] *= al0;
                o[nt][2] *= al1; o[nt][3] *= al1;
            }
            #pragma unroll
            for (int st = 0; st < 4; st++) {
                uint32_t soff = st * 16 * 2;
                uint32_t ah[4], al_[4], bh[2][4], bl[2][4];
                ldsm4(ah, uP + pv_a_off + soff);
                ldsm4(al_, uP + SIDEB + pv_a_off + soff);
                #pragma unroll
                for (int h = 0; h < 2; h++) {
                    ldsm4(bh[h], uV + pv_b_off[h] + soff);
                    ldsm4(bl[h], uV + SIDEB + pv_b_off[h] + soff);
                }
                #pragma unroll
                for (int nt = 0; nt < 4; nt++) {
                    uint32_t* B_h = &bh[nt >> 1][(nt & 1) * 2];
                    uint32_t* B_l = &bl[nt >> 1][(nt & 1) * 2];
                    mma16816(o[nt], ah, B_h);
                    mma16816(o[nt], al_, B_h);
                    mma16816(o[nt], ah, B_l);
                }
            }
        }
        __syncthreads();
    }

    // normalize + stage [c][q] f32, then split-store planes
    {
        float li0 = 1.f / l_s[qbase + (lane >> 2)];
        float li1 = 1.f / l_s[qbase + (lane >> 2) + 8];
        int qq = qbase + (lane >> 2);
        #pragma unroll
        for (int nt = 0; nt < 4; nt++) {
            int c0 = ws * 32 + nt * 8 + (lane & 3) * 2;
            sS[c0 * 68 + qq] = o[nt][0] * li0;
            sS[(c0 + 1) * 68 + qq] = o[nt][1] * li0;
            sS[c0 * 68 + qq + 8] = o[nt][2] * li1;
            sS[(c0 + 1) * 68 + qq + 8] = o[nt][3] * li1;
        }
    }
    __syncthreads();
    size_t obase = ((size_t)b * CC + (size_t)hd * 64) * TT + q0g;
    #pragma unroll
    for (int it = 0; it < 4; it++) {
        int e = tid + it * 256;
        int cch = e >> 4, q4 = e & 15;
        float4 v = *(const float4*)&sS[cch * 68 + q4 * 4];
        uint32_t h0, l0, h1, l1;
        split2(v.x, v.y, h0, l0); split2(v.z, v.w, h1, l1);
        *(uint2*)&ath[obase + (size_t)cch * TT + q4 * 4] = make_uint2(h0, h1);
        *(uint2*)&atl[obase + (size_t)cch * TT + q4 * 4] = make_uint2(l0, l1);
    }
}

// ---------------------------------------------------------------------------
extern "C" void kernel_launch(void* const* d_in, const int* in_sizes, int n_in,
                              void* d_out, int out_size) {
    const float* x = (const float*)d_in[0];
    const float* gn_scale = (const float*)d_in[1];
    const float* gn_bias = (const float*)d_in[2];
    const float* w_qkv = (const float*)d_in[3];
    const float* b_qkv = (const float*)d_in[4];
    const float* w_proj = (const float*)d_in[5];
    const float* b_proj = (const float*)d_in[6];
    float* out = (float*)d_out;

    bf16 *xnh, *xnl, *qkvh, *qkvl, *ath, *atl;
    cudaGetSymbolAddress((void**)&xnh, g_xn_h);
    cudaGetSymbolAddress((void**)&xnl, g_xn_l);
    cudaGetSymbolAddress((void**)&qkvh, g_qkv_h);
    cudaGetSymbolAddress((void**)&qkvl, g_qkv_l);
    cudaGetSymbolAddress((void**)&ath, g_at_h);
    cudaGetSymbolAddress((void**)&atl, g_at_l);

    cudaFuncSetAttribute(attn_mma, cudaFuncAttributeMaxDynamicSharedMemorySize,
                         ATTN_SMEM);

    gn_kernel<<<BB * NG, 256>>>(x, gn_scale, gn_bias, xnh, xnl);
    gemm_mma<true><<<dim3(TT / 128, (3 * CC) / 128, BB), 256>>>(
        w_qkv, xnh, xnl, b_qkv, nullptr, nullptr, qkvh, qkvl, 3 * CC, CC);
    attn_mma<<<dim3(TT / 64, BB * NH), 256, ATTN_SMEM>>>(qkvh, qkvl, ath, atl);
    gemm_mma<false><<<dim3(TT / 128, CC / 128, BB), 256>>>(
        w_proj, ath, atl, b_proj, x, out, nullptr, nullptr, CC, CC);
}